// round 9
// baseline (speedup 1.0000x reference)
#include <cuda_runtime.h>
#include <cstdint>

#define EPS 1e-5f
#define Nn 8
#define Cc 256
#define Hh 64
#define Ww 64
#define HW 4096
#define OC 64
#define Pp 36

typedef unsigned long long u64;
typedef unsigned int u32;
typedef unsigned short u16;

// softmax weights scratch, layout [n][h][36][w] (w contiguous)
__device__ float g_wts[(size_t)Nn * HW * Pp];

__device__ __forceinline__ u64 pack2(float x, float y) {
    u64 r; asm("mov.b64 %0, {%1,%2};" : "=l"(r) : "f"(x), "f"(y)); return r;
}
__device__ __forceinline__ void fma2(u64 &d, u64 a, u64 b) {
    asm("fma.rn.f32x2 %0, %1, %2, %0;" : "+l"(d) : "l"(a), "l"(b));
}
__device__ __forceinline__ float2 unpack2(u64 v) {
    float2 r; asm("mov.b64 {%0,%1}, %2;" : "=f"(r.x), "=f"(r.y) : "l"(v)); return r;
}
__device__ __forceinline__ u32 smem_u32(const void* p) {
    u32 a;
    asm("{ .reg .u64 t; cvta.to.shared.u64 t, %1; cvt.u32.u64 %0, t; }" : "=r"(a) : "l"(p));
    return a;
}
__device__ __forceinline__ void ldsm4(u32& r0, u32& r1, u32& r2, u32& r3, u32 addr) {
    asm volatile("ldmatrix.sync.aligned.m8n8.x4.shared.b16 {%0,%1,%2,%3}, [%4];"
                 : "=r"(r0), "=r"(r1), "=r"(r2), "=r"(r3) : "r"(addr));
}
__device__ __forceinline__ void ldsm4t(u32& r0, u32& r1, u32& r2, u32& r3, u32 addr) {
    asm volatile("ldmatrix.sync.aligned.m8n8.x4.trans.shared.b16 {%0,%1,%2,%3}, [%4];"
                 : "=r"(r0), "=r"(r1), "=r"(r2), "=r"(r3) : "r"(addr));
}
__device__ __forceinline__ void mma16816(float* c, u32 a0, u32 a1, u32 a2, u32 a3,
                                          u32 b0, u32 b1) {
    asm volatile("mma.sync.aligned.m16n8k16.row.col.f32.bf16.bf16.f32 "
                 "{%0,%1,%2,%3}, {%4,%5,%6,%7}, {%8,%9}, {%0,%1,%2,%3};"
                 : "+f"(c[0]), "+f"(c[1]), "+f"(c[2]), "+f"(c[3])
                 : "r"(a0), "r"(a1), "r"(a2), "r"(a3), "r"(b0), "r"(b1));
}
__device__ __forceinline__ void split2(float vx, float vy, u32& hi, u32& lo) {
    u32 h; asm("cvt.rn.bf16x2.f32 %0, %1, %2;" : "=r"(h) : "f"(vy), "f"(vx));
    float hx = __uint_as_float(h << 16);
    float hy = __uint_as_float(h & 0xffff0000u);
    u32 l; asm("cvt.rn.bf16x2.f32 %0, %1, %2;" : "=r"(l) : "f"(vy - hy), "f"(vx - hx));
    hi = h; lo = l;
}
__device__ __forceinline__ u16 bf16hi(float v) {
    u16 h; asm("cvt.rn.bf16.f32 %0, %1;" : "=h"(h) : "f"(v)); return h;
}

// ---------------------------------------------------------------------------
// Kernel 1: weights. GEMM0 + encoder both on mma.sync (unchanged from R8
// except the g_wts dump layout).
// ---------------------------------------------------------------------------
#define S_AHI   0
#define S_ALO   34816
#define S_WHI   69632
#define S_WLO   87040
#define S_CST   104448
#define SMEM1   105280

#define S2_AHI  0
#define S2_ALO  17408
#define S2_WHI  34816
#define S2_WLO  47872
#define S2_L    60928
#define S2_WTS  0

extern "C" __global__ void __launch_bounds__(256, 2)
k_weights(const float* __restrict__ x,
          const float* __restrict__ w0, const float* __restrict__ b0,
          const float* __restrict__ bn0_g, const float* __restrict__ bn0_b,
          const float* __restrict__ bn0_m, const float* __restrict__ bn0_v,
          const float* __restrict__ w1, const float* __restrict__ b1,
          const float* __restrict__ bn1_g, const float* __restrict__ bn1_b,
          const float* __restrict__ bn1_m, const float* __restrict__ bn1_v)
{
    extern __shared__ char smem[];
    const u32 sb = smem_u32(smem);
    float* cA0 = (float*)(smem + S_CST);
    float* cB0 = cA0 + 64;
    float* cA1 = cB0 + 64;
    float* cB1 = cA1 + 40;
    float* wts_s = (float*)(smem + S2_WTS);
    float* L     = (float*)(smem + S2_L);

    const int t = threadIdx.x;
    const int warp = t >> 5, lane = t & 31;
    const int n = blockIdx.y, p0 = blockIdx.x * 128;

    if (t < 64) {
        float A = bn0_g[t] * rsqrtf(bn0_v[t] + EPS);
        cA0[t] = A;
        cB0[t] = (b0[t] - bn0_m[t]) * A + bn0_b[t];
    } else if (t < 64 + 40) {
        int i = t - 64;
        if (i < Pp) {
            float A = bn1_g[i] * rsqrtf(bn1_v[i] + EPS);
            cA1[i] = A;
            cB1[i] = (b1[i] - bn1_m[i]) * A + bn1_b[i];
        } else { cA1[i] = 0.f; cB1[i] = 0.f; }
    }

    // prefetch w1 into registers (staged to smem after GEMM0)
    float2 w1r[5];
    #pragma unroll
    for (int r = 0; r < 5; r++) {
        int i = t + 256 * r;
        w1r[r] = *(const float2*)(w1 + (i >> 5) * OC + (i & 31) * 2);
    }

    const int mat = lane >> 3, mr = lane & 7;
    const int m0 = warp * 16;
    const int g  = lane >> 2, tq = lane & 3;
    const u32 a_off = (u32)((((mat >> 1) * 8) + mr) * 272 + (m0 + (mat & 1) * 8) * 2);
    const u32 b_off = (u32)((((mat >> 1) * 8) + mr) * 272 + (mat & 1) * 16);

    float acc[8][4];
    #pragma unroll
    for (int i = 0; i < 8; i++)
        #pragma unroll
        for (int j = 0; j < 4; j++) acc[i][j] = 0.f;

    // ================= GEMM0: two K-halves =================
    #pragma unroll 1
    for (int h = 0; h < 2; h++) {
        __syncthreads();
        {
            const float2* xr = (const float2*)(x + ((size_t)n * Cc + h * 128 + warp * 16) * HW + p0);
            char* ahb = smem + S_AHI + (warp * 16) * 272 + lane * 4;
            char* alb = smem + S_ALO + (warp * 16) * 272 + lane * 4;
            #pragma unroll 4
            for (int rr = 0; rr < 16; rr++) {
                float2 v0 = xr[lane];
                float2 v1 = xr[lane + 32];
                u32 h0, l0, h1, l1;
                split2(v0.x, v0.y, h0, l0);
                split2(v1.x, v1.y, h1, l1);
                *(u32*)(ahb)       = h0;
                *(u32*)(ahb + 128) = h1;
                *(u32*)(alb)       = l0;
                *(u32*)(alb + 128) = l1;
                xr += HW / 2;
                ahb += 272; alb += 272;
            }
        }
        {
            const int cq = t & 63;
            #pragma unroll 4
            for (int it = 0; it < 16; it++) {
                int oc = it * 4 + (t >> 6);
                float2 v = *(const float2*)(w0 + (size_t)oc * Cc + h * 128 + cq * 2);
                u32 hi, lo;
                split2(v.x, v.y, hi, lo);
                *(u32*)(smem + S_WHI + oc * 272 + cq * 4) = hi;
                *(u32*)(smem + S_WLO + oc * 272 + cq * 4) = lo;
            }
        }
        __syncthreads();

        #pragma unroll
        for (int ks = 0; ks < 8; ks++) {
            u32 ah0, ah1, ah2, ah3, al0, al1, al2, al3;
            ldsm4t(ah0, ah1, ah2, ah3, sb + S_AHI + ks * 4352 + a_off);
            ldsm4t(al0, al1, al2, al3, sb + S_ALO + ks * 4352 + a_off);
            #pragma unroll
            for (int j = 0; j < 4; j++) {
                u32 bh0, bh1, bh2, bh3, bl0, bl1, bl2, bl3;
                ldsm4(bh0, bh1, bh2, bh3, sb + S_WHI + j * 16 * 272 + ks * 32 + b_off);
                ldsm4(bl0, bl1, bl2, bl3, sb + S_WLO + j * 16 * 272 + ks * 32 + b_off);
                mma16816(acc[2 * j],     ah0, ah1, ah2, ah3, bh0, bh1);
                mma16816(acc[2 * j],     al0, al1, al2, al3, bh0, bh1);
                mma16816(acc[2 * j],     ah0, ah1, ah2, ah3, bl0, bl1);
                mma16816(acc[2 * j + 1], ah0, ah1, ah2, ah3, bh2, bh3);
                mma16816(acc[2 * j + 1], al0, al1, al2, al3, bh2, bh3);
                mma16816(acc[2 * j + 1], ah0, ah1, ah2, ah3, bl2, bl3);
            }
        }
    }
    __syncthreads();

    // ---- epilogue: BN0 + ReLU -> As2[oc][px] bf16 hi/lo directly ----
    {
        const int pxa = m0 + g, pxb = m0 + g + 8;
        #pragma unroll
        for (int j = 0; j < 8; j++) {
            int oc0 = 8 * j + 2 * tq, oc1 = oc0 + 1;
            float Aa = cA0[oc0], Ba = cB0[oc0];
            float Ab = cA0[oc1], Bb = cB0[oc1];
            float v00 = fmaxf(fmaf(acc[j][0], Aa, Ba), 0.f);
            float v01 = fmaxf(fmaf(acc[j][1], Ab, Bb), 0.f);
            float v10 = fmaxf(fmaf(acc[j][2], Aa, Ba), 0.f);
            float v11 = fmaxf(fmaf(acc[j][3], Ab, Bb), 0.f);
            #pragma unroll
            for (int q = 0; q < 4; q++) {
                float v  = (q == 0) ? v00 : (q == 1) ? v01 : (q == 2) ? v10 : v11;
                int oc   = (q & 1) ? oc1 : oc0;
                int px   = (q & 2) ? pxb : pxa;
                u16 hi = bf16hi(v);
                float hf = __uint_as_float(((u32)hi) << 16);
                u16 lo = bf16hi(v - hf);
                *(u16*)(smem + S2_AHI + oc * 272 + px * 2) = hi;
                *(u16*)(smem + S2_ALO + oc * 272 + px * 2) = lo;
            }
        }
    }
    // ---- stage Ws2 from prefetched w1 regs ----
    #pragma unroll
    for (int r = 0; r < 5; r++) {
        int i = t + 256 * r;
        int p = i >> 5, oq = i & 31;
        u32 hi, lo;
        split2(w1r[r].x, w1r[r].y, hi, lo);
        *(u32*)(smem + S2_WHI + p * 272 + oq * 4) = hi;
        *(u32*)(smem + S2_WLO + p * 272 + oq * 4) = lo;
    }
    for (int i = t; i < 8 * 68; i += 256) {
        int row = 40 + i / 68, col = i % 68;
        *(u32*)(smem + S2_WHI + row * 272 + col * 4) = 0;
        *(u32*)(smem + S2_WLO + row * 272 + col * 4) = 0;
    }
    __syncthreads();

    // ================= MMA1: logits [128, 40] =================
    float d1[5][4];
    #pragma unroll
    for (int i = 0; i < 5; i++)
        #pragma unroll
        for (int j = 0; j < 4; j++) d1[i][j] = 0.f;

    #pragma unroll
    for (int ks = 0; ks < 4; ks++) {
        u32 ah0, ah1, ah2, ah3, al0, al1, al2, al3;
        ldsm4t(ah0, ah1, ah2, ah3, sb + S2_AHI + ks * 4352 + a_off);
        ldsm4t(al0, al1, al2, al3, sb + S2_ALO + ks * 4352 + a_off);
        #pragma unroll
        for (int rb = 0; rb < 3; rb++) {
            u32 bh0, bh1, bh2, bh3, bl0, bl1, bl2, bl3;
            ldsm4(bh0, bh1, bh2, bh3, sb + S2_WHI + rb * 4352 + ks * 32 + b_off);
            ldsm4(bl0, bl1, bl2, bl3, sb + S2_WLO + rb * 4352 + ks * 32 + b_off);
            int nt = 2 * rb;
            mma16816(d1[nt], ah0, ah1, ah2, ah3, bh0, bh1);
            mma16816(d1[nt], al0, al1, al2, al3, bh0, bh1);
            mma16816(d1[nt], ah0, ah1, ah2, ah3, bl0, bl1);
            if (rb < 2) {
                mma16816(d1[nt + 1], ah0, ah1, ah2, ah3, bh2, bh3);
                mma16816(d1[nt + 1], al0, al1, al2, al3, bh2, bh3);
                mma16816(d1[nt + 1], ah0, ah1, ah2, ah3, bl2, bl3);
            }
        }
    }
    #pragma unroll
    for (int nt = 0; nt < 5; nt++) {
        int pc0 = 8 * nt + 2 * tq, pc1 = pc0 + 1;
        float Aa = cA1[pc0], Ba = cB1[pc0];
        float Ab = cA1[pc1], Bb = cB1[pc1];
        L[(m0 + g) * 49 + pc0]     = fmaxf(fmaf(d1[nt][0], Aa, Ba), 0.f);
        L[(m0 + g) * 49 + pc1]     = fmaxf(fmaf(d1[nt][1], Ab, Bb), 0.f);
        L[(m0 + g + 8) * 49 + pc0] = fmaxf(fmaf(d1[nt][2], Aa, Ba), 0.f);
        L[(m0 + g + 8) * 49 + pc1] = fmaxf(fmaf(d1[nt][3], Ab, Bb), 0.f);
    }
    __syncthreads();

    // ---- softmax over k (9) for u = hh, hh+2 ----
    {
        const int px = t & 127;
        const int hh = t >> 7;
        const float* Lp = L + px * 49;
        #pragma unroll
        for (int uu = 0; uu < 2; uu++) {
            int u = hh + 2 * uu;
            float e[9], mx = -1e30f;
            #pragma unroll
            for (int k = 0; k < 9; k++) { e[k] = Lp[k * 4 + u]; mx = fmaxf(mx, e[k]); }
            float s = 0.f;
            #pragma unroll
            for (int k = 0; k < 9; k++) { float q = __expf(e[k] - mx); e[k] = q; s += q; }
            float inv = 1.f / s;
            #pragma unroll
            for (int k = 0; k < 9; k++) wts_s[px * 37 + k * 4 + u] = e[k] * inv;
        }
    }
    __syncthreads();

    // ---- dump to g_wts in [n][h][36][w] layout (block = 2 full w-rows) ----
    {
        const int hrow = p0 >> 6;   // first of the 2 h-rows this block owns
        float* gb = g_wts + (size_t)(n * Hh + hrow) * (36 * 64);
        // i enumerates [r][c][w]; lanes consecutive in w -> coalesced STG
        for (int i = t; i < 2 * 36 * 64; i += 256) {
            int w = i & 63;
            int c = (i >> 6) % 36;
            int r = i / (36 * 64);
            gb[(size_t)(r * 36 + c) * 64 + w] = wts_s[(r * 64 + w) * 37 + c];
        }
    }
}

// ---------------------------------------------------------------------------
// Kernel 2: reassembly + pixelshuffle. c-split=4 (64 ch/block), coalesced
// per-pixel weight fetch from [n][h][36][w] layout, 3-stage cp.async pipe.
// ---------------------------------------------------------------------------
__device__ __forceinline__ void cp_async16(u32 dst, const void* src, u32 srcsz) {
    asm volatile("cp.async.cg.shared.global [%0], [%1], 16, %2;"
                 :: "r"(dst), "l"(src), "r"(srcsz));
}
__device__ __forceinline__ void cp_commit() { asm volatile("cp.async.commit_group;"); }
__device__ __forceinline__ void cp_wait1() { asm volatile("cp.async.wait_group 1;" ::: "memory"); }
__device__ __forceinline__ void cp_wait0() { asm volatile("cp.async.wait_group 0;" ::: "memory"); }
__device__ __forceinline__ void stcs2(float* p, float2 v) {
    asm volatile("st.global.cs.v2.f32 [%0], {%1,%2};" :: "l"(p), "f"(v.x), "f"(v.y));
}

#define ROWF    40
#define CHUNK_B (8 * 10 * ROWF * 4)   // 12800 B

extern "C" __global__ void __launch_bounds__(256)
k_reassemble(const float* __restrict__ x, float* __restrict__ out)
{
    __shared__ float xs[3][8][10][ROWF];

    const int tid = threadIdx.x;
    const int tx   = tid & 31;
    const int warp = tid >> 5;
    const int w0p = blockIdx.x * 32;
    const int h0  = blockIdx.y * 8;
    const int n   = blockIdx.z >> 2;
    const int c0  = (blockIdx.z & 3) * 64;
    const int h   = h0 + warp;
    const int w   = w0p + tx;

    const float* xb = x + (size_t)n * Cc * HW;
    u32 s_base = (u32)__cvta_generic_to_shared(&xs[0][0][0][0]);

    const float* gWarp = xb + (size_t)(c0 + warp) * HW + (h0 - 1) * Ww + (w0p - 4);
    u32  smOff[4];
    int  gOff[4];
    bool pred[4], act[4];
    #pragma unroll
    for (int i = 0; i < 4; i++) {
        int idx = i * 32 + tx;
        act[i] = idx < 100;
        int row = idx / 10, j = idx - row * 10;
        int v = w0p - 4 + 4 * j;
        bool rok = ((unsigned)(h0 - 1 + row) < (unsigned)Hh);
        bool cok = ((unsigned)v <= 60u);
        pred[i]  = act[i] && rok && cok;
        smOff[i] = (u32)((warp * 10 * ROWF + row * ROWF + 4 * j) * 4);
        gOff[i]  = row * Ww + 4 * j;
    }

    // prefetch chunks 0 and 1
    #pragma unroll
    for (int c = 0; c < 2; c++) {
        const float* gch = gWarp + (size_t)c * 8 * HW;
        u32 sb2 = s_base + c * CHUNK_B;
        #pragma unroll
        for (int i = 0; i < 4; i++)
            if (act[i]) cp_async16(sb2 + smOff[i], pred[i] ? gch + gOff[i] : xb,
                                   pred[i] ? 16u : 0u);
        cp_commit();
    }

    // per-pixel softmax weights: [n][h][36][w] -> 36 lane-coalesced LDG.32
    const float* wb = g_wts + (size_t)(n * Hh + h) * (36 * 64) + w;
    u64 wp01[9], wp23[9];
    #pragma unroll
    for (int k = 0; k < 9; k++) {
        float a0 = __ldg(wb + (k * 4 + 0) * 64);
        float a1 = __ldg(wb + (k * 4 + 1) * 64);
        float a2 = __ldg(wb + (k * 4 + 2) * 64);
        float a3 = __ldg(wb + (k * 4 + 3) * 64);
        wp01[k] = pack2(a0, a1);
        wp23[k] = pack2(a2, a3);
    }

    const int ty = warp;
    float* op = out + (size_t)n * Cc * (HW * 4)
                    + (size_t)c0 * (HW * 4) + (2 * h) * 128 + 2 * w;

    #pragma unroll 1
    for (int ch8 = 0; ch8 < 8; ch8++) {
        if (ch8 == 7) cp_wait0(); else cp_wait1();
        __syncthreads();

        if (ch8 < 6) {
            const float* gch = gWarp + (size_t)(ch8 + 2) * 8 * HW;
            u32 sb2 = s_base + ((ch8 + 2) % 3) * CHUNK_B;
            #pragma unroll
            for (int i = 0; i < 4; i++)
                if (act[i]) cp_async16(sb2 + smOff[i], pred[i] ? gch + gOff[i] : xb,
                                       pred[i] ? 16u : 0u);
            cp_commit();
        }

        const int b = ch8 % 3;
        #pragma unroll
        for (int cl = 0; cl < 8; cl++) {
            u64 a01 = 0ULL, a23 = 0ULL;
            #pragma unroll
            for (int dy = 0; dy < 3; dy++) {
                #pragma unroll
                for (int dx = 0; dx < 3; dx++) {
                    float xv = xs[b][cl][ty + dy][tx + 3 + dx];
                    u64 xp = pack2(xv, xv);
                    int k = dy * 3 + dx;
                    fma2(a01, xp, wp01[k]);
                    fma2(a23, xp, wp23[k]);
                }
            }
            stcs2(op,       unpack2(a01));
            stcs2(op + 128, unpack2(a23));
            op += HW * 4;
        }
    }
}

extern "C" void kernel_launch(void* const* d_in, const int* in_sizes, int n_in,
                              void* d_out, int out_size)
{
    const float* x     = (const float*)d_in[0];
    const float* w0    = (const float*)d_in[1];
    const float* b0    = (const float*)d_in[2];
    const float* bn0_g = (const float*)d_in[3];
    const float* bn0_b = (const float*)d_in[4];
    const float* bn0_m = (const float*)d_in[5];
    const float* bn0_v = (const float*)d_in[6];
    const float* w1    = (const float*)d_in[7];
    const float* b1    = (const float*)d_in[8];
    const float* bn1_g = (const float*)d_in[9];
    const float* bn1_b = (const float*)d_in[10];
    const float* bn1_m = (const float*)d_in[11];
    const float* bn1_v = (const float*)d_in[12];
    float* out = (float*)d_out;

    cudaFuncSetAttribute(k_weights, cudaFuncAttributeMaxDynamicSharedMemorySize, SMEM1);
    dim3 g1(32, Nn);
    k_weights<<<g1, 256, SMEM1>>>(x, w0, b0, bn0_g, bn0_b, bn0_m, bn0_v,
                                  w1, b1, bn1_g, bn1_b, bn1_m, bn1_v);

    dim3 g2(2, 8, Nn * 4);
    k_reassemble<<<g2, 256>>>(x, out);
}